// round 16
// baseline (speedup 1.0000x reference)
#include <cuda_runtime.h>
#include <cuda_bf16.h>
#include <cstdint>

#define N_NODES 100000
#define N_EDGES 200000
#define D_NODE 128
#define D_EDGE 16
#define N_REL 3
#define TILES 782
#define CAP 1024
#define A_RSTRIDE ((size_t)TILES * 128 * 128)   // padded per-relation stride

// ───────────────────────── scratch ─────────────────────────
__device__ float    g_A[(size_t)N_REL * A_RSTRIDE];        // 153.7 MB, written by atile (no zero)
__device__ float    g_E2[(size_t)N_NODES * 64];            // packed E, 25.6 MB (L2-resident)
__device__ int      g_bcnt[N_REL * TILES];
__device__ uint32_t g_brec[(size_t)N_REL * TILES * CAP];   // (src<<7)|row
__device__ int2     g_ovf[N_REL * N_EDGES];                // (key, rec) overflow, worst-case safe
__device__ int      g_ovfcnt;
__device__ __nv_bfloat16 g_Wh[9 * 128 * 64];
__device__ __nv_bfloat16 g_Wl[9 * 128 * 64];

// ─────────────── prep: zero E2+bcnt, split weights ───────────────
__global__ void prep_kernel(const float* __restrict__ W_rel,
                            const float* __restrict__ We_rel,
                            const float* __restrict__ W_self) {
    int gtid = blockIdx.x * blockDim.x + threadIdx.x;
    if (gtid == 0) g_ovfcnt = 0;

    if (gtid < 9 * 128 * 64) {
        int c = gtid / (128 * 64);
        int rem = gtid - c * (128 * 64);
        int n = rem >> 6, j = rem & 63;
        float v = 0.f;
        if (c < 2)       v = W_self[(c * 64 + j) * 128 + n];
        else if (c < 8)  { int r = (c - 2) >> 1, h = (c - 2) & 1;
                           v = W_rel[r * 16384 + (h * 64 + j) * 128 + n]; }
        else             { if (j < 48) v = We_rel[(j >> 4) * 2048 + (j & 15) * 128 + n]; }
        __nv_bfloat16 hb = __float2bfloat16_rn(v);
        g_Wh[gtid] = hb;
        g_Wl[gtid] = __float2bfloat16_rn(v - __bfloat162float(hb));
    }

    size_t stride = (size_t)gridDim.x * blockDim.x;
    const size_t nE = (size_t)N_NODES * 64 / 4;
    float4 z = make_float4(0.f, 0.f, 0.f, 0.f);
    float4* E4 = reinterpret_cast<float4*>(g_E2);
    for (size_t i = gtid; i < nE; i += stride) E4[i] = z;
    for (int i = gtid; i < N_REL * TILES; i += (int)stride) g_bcnt[i] = 0;
}

// ───────────── bucket: bin edges by (rel, dst-tile) ─────────────
__global__ void bucket_kernel(const int* __restrict__ edge_index) {
    int w = blockIdx.x * blockDim.x + threadIdx.x;
    if (w >= N_REL * N_EDGES) return;
    int r = w / N_EDGES;
    int2 se = reinterpret_cast<const int2*>(edge_index)[w];
    int key = r * TILES + (se.y >> 7);
    uint32_t rec = ((uint32_t)se.x << 7) | (uint32_t)(se.y & 127);
    int pos = atomicAdd(&g_bcnt[key], 1);
    if (pos < CAP) g_brec[(size_t)key * CAP + pos] = rec;
    else {
        int o = atomicAdd(&g_ovfcnt, 1);
        g_ovf[o] = make_int2(key, (int)rec);
    }
}

// ───────────── escatter: g_E2[dst][r*16..] += edge_attr ─────────────
__global__ void escatter_kernel(const float* __restrict__ edge_attr,
                                const int*   __restrict__ edge_index) {
    int idx = blockIdx.x * blockDim.x + threadIdx.x;
    if (idx >= N_REL * N_EDGES * 4) return;
    int w = idx >> 2, q = idx & 3;
    int r = w / N_EDGES;
    int dst = edge_index[2 * w + 1];
    float4 u = reinterpret_cast<const float4*>(edge_attr)[(size_t)w * 4 + q];
    float* ep = g_E2 + (size_t)dst * 64 + r * 16 + q * 4;
    asm volatile("red.global.add.v4.f32 [%0], {%1,%2,%3,%4};"
                 :: "l"(ep), "f"(u.x), "f"(u.y), "f"(u.z), "f"(u.w) : "memory");
}

// ───────── atile: per-(rel,tile) CTA builds A tile in registers, plain store ──
__global__ __launch_bounds__(256) void atile_kernel(const float* __restrict__ x) {
    __shared__ uint32_t srec[CAP];
    int key = blockIdx.x;
    int t = threadIdx.x;

    int cnt = g_bcnt[key];
    if (cnt > CAP) cnt = CAP;
    const uint32_t* rec = g_brec + (size_t)key * CAP;
    for (int i = t; i < cnt; i += 256) srec[i] = rec[i];
    __syncthreads();

    int row = t >> 1, half = t & 1;            // 2 threads per row, 64 floats each
    const float4* x4 = reinterpret_cast<const float4*>(x);

    float4 acc[16];
#pragma unroll
    for (int q = 0; q < 16; ++q) acc[q] = make_float4(0.f, 0.f, 0.f, 0.f);

    for (int i = 0; i < cnt; ++i) {
        uint32_t rv = srec[i];
        if ((int)(rv & 127u) == row) {
            const float4* xs = x4 + (size_t)(rv >> 7) * 32 + half * 16;
#pragma unroll
            for (int q = 0; q < 16; ++q) {
                float4 u = xs[q];
                acc[q].x += u.x; acc[q].y += u.y; acc[q].z += u.z; acc[q].w += u.w;
            }
        }
    }

    float4* dst = reinterpret_cast<float4*>(g_A) + (size_t)key * 4096 + row * 32 + half * 16;
#pragma unroll
    for (int q = 0; q < 16; ++q) dst[q] = acc[q];
}

// ───────────── overflow: rare deg-overflow edges via atomics (after atile) ────
__global__ void overflow_kernel(const float* __restrict__ x) {
    int nw = (gridDim.x * blockDim.x) >> 5;
    int w = (blockIdx.x * blockDim.x + threadIdx.x) >> 5;
    int lane = threadIdx.x & 31;
    int total = g_ovfcnt;
    const float4* x4 = reinterpret_cast<const float4*>(x);
    for (int i = w; i < total; i += nw) {
        int2 o = g_ovf[i];
        int row = o.y & 127, src = o.y >> 7;
        float4 u = x4[(size_t)src * 32 + lane];
        float* a = g_A + ((size_t)o.x * 128 + row) * 128 + lane * 4;
        asm volatile("red.global.add.v4.f32 [%0], {%1,%2,%3,%4};"
                     :: "l"(a), "f"(u.x), "f"(u.y), "f"(u.z), "f"(u.w) : "memory");
    }
}

// ───────────────── bf16x3 GEMM, full double-buffer + swizzle (R13) ────────────
__device__ __forceinline__ uint32_t smem_u32(const void* p) {
    uint32_t a;
    asm("{ .reg .u64 t; cvta.to.shared.u64 t, %1; cvt.u32.u64 %0, t; }" : "=r"(a) : "l"(p));
    return a;
}
__device__ __forceinline__ void ldsm4(uint32_t* r, uint32_t addr) {
    asm volatile("ldmatrix.sync.aligned.m8n8.x4.shared.b16 {%0,%1,%2,%3}, [%4];"
                 : "=r"(r[0]), "=r"(r[1]), "=r"(r[2]), "=r"(r[3]) : "r"(addr));
}
__device__ __forceinline__ void cpa16(uint32_t s, const void* g) {
    asm volatile("cp.async.ca.shared.global [%0], [%1], 16;" :: "r"(s), "l"(g));
}
__device__ __forceinline__ void mma16816(float* c, const uint32_t* a,
                                         uint32_t b0, uint32_t b1) {
    asm volatile(
        "mma.sync.aligned.m16n8k16.row.col.f32.bf16.bf16.f32 "
        "{%0,%1,%2,%3}, {%4,%5,%6,%7}, {%8,%9}, {%0,%1,%2,%3};"
        : "+f"(c[0]), "+f"(c[1]), "+f"(c[2]), "+f"(c[3])
        : "r"(a[0]), "r"(a[1]), "r"(a[2]), "r"(a[3]), "r"(b0), "r"(b1));
}
__device__ __forceinline__ void split8(const float* f, uint4& hi, uint4& lo) {
    uint32_t h[8], l[8];
#pragma unroll
    for (int j = 0; j < 8; ++j) {
        __nv_bfloat16 hb = __float2bfloat16_rn(f[j]);
        float r = f[j] - __bfloat162float(hb);
        __nv_bfloat16 lb = __float2bfloat16_rn(r);
        h[j] = (uint32_t)__bfloat16_as_ushort(hb);
        l[j] = (uint32_t)__bfloat16_as_ushort(lb);
    }
    hi.x = h[0] | (h[1] << 16); hi.y = h[2] | (h[3] << 16);
    hi.z = h[4] | (h[5] << 16); hi.w = h[6] | (h[7] << 16);
    lo.x = l[0] | (l[1] << 16); lo.y = l[2] | (l[3] << 16);
    lo.z = l[4] | (l[5] << 16); lo.w = l[6] | (l[7] << 16);
}

static constexpr int STAGE    = 65536;
static constexpr int OFF_AH   = 0;
static constexpr int OFF_AL   = 16384;
static constexpr int OFF_BH   = 32768;
static constexpr int OFF_BL   = 49152;
static constexpr int SMEM_TOTAL = 2 * STAGE;   // 131072

static constexpr int NC = 9;

struct Chunk { const float* a; int ld, kb; };

__device__ __forceinline__ Chunk chunk_desc(int c, const float* x) {
    Chunk d;
    if (c < 2)      { d.a = x; d.ld = 128; d.kb = c * 64; }
    else if (c < 8) { int r = (c - 2) >> 1, h = (c - 2) & 1;
                      d.a = g_A + (size_t)r * A_RSTRIDE; d.ld = 128; d.kb = h * 64; }
    else            { d.a = g_E2; d.ld = 64; d.kb = 0; }
    return d;
}

__global__ __launch_bounds__(256, 1) void gemm_mma_kernel(
    const float* __restrict__ x,
    const float* __restrict__ bias,
    float* __restrict__ out) {
    extern __shared__ char smem[];
    uint32_t sbase = smem_u32(smem);

    int t = threadIdx.x;
    int wid = t >> 5, lane = t & 31;
    int wm = wid & 3, wn = wid >> 2;
    int m0 = blockIdx.x * 128;

    uint32_t xorv = (uint32_t)(lane & 7) << 4;
    int arow = (lane & 7) + ((lane & 8) ? 8 : 0);
    uint32_t acb = (lane & 16) ? 16 : 0;
    uint32_t aRowByte0 = (uint32_t)(wm * 32 + arow) * 128;
    int brow = (lane & 7) + ((lane & 16) ? 8 : 0);
    uint32_t bcb = (lane & 8) ? 16 : 0;
    uint32_t bRowByte0 = (uint32_t)(wn * 64 + brow) * 128;

    int aRow = t >> 1, aHalf = t & 1;
    uint32_t aStoreRow = (uint32_t)aRow * 128;
    uint32_t aStoreXor = (uint32_t)(aRow & 7) << 4;
    float4 ar[8];

    auto load_a = [&](int c) {
        Chunk d = chunk_desc(c, x);
        int gr = m0 + aRow;
        const float* ap = d.a + (size_t)gr * d.ld + d.kb + aHalf * 32;
        if (gr < N_NODES) {
#pragma unroll
            for (int q = 0; q < 8; ++q)
                ar[q] = *reinterpret_cast<const float4*>(ap + q * 4);
        } else {
#pragma unroll
            for (int q = 0; q < 8; ++q) ar[q] = make_float4(0.f, 0.f, 0.f, 0.f);
        }
    };
    auto store_a = [&](int stage) {
        char* base = smem + stage * STAGE;
#pragma unroll
        for (int g = 0; g < 4; ++g) {
            float f[8];
            f[0]=ar[g*2].x; f[1]=ar[g*2].y; f[2]=ar[g*2].z; f[3]=ar[g*2].w;
            f[4]=ar[g*2+1].x; f[5]=ar[g*2+1].y; f[6]=ar[g*2+1].z; f[7]=ar[g*2+1].w;
            uint4 hi, lo; split8(f, hi, lo);
            uint32_t cbyte = (uint32_t)(64 * aHalf + 16 * g);
            uint32_t off = aStoreRow + (cbyte ^ aStoreXor);
            *reinterpret_cast<uint4*>(base + OFF_AH + off) = hi;
            *reinterpret_cast<uint4*>(base + OFF_AL + off) = lo;
        }
    };
    auto issue_b = [&](int c, int stage) {
        uint32_t bb = sbase + stage * STAGE;
        const __nv_bfloat16* gh = g_Wh + c * 8192;
        const __nv_bfloat16* gl = g_Wl + c * 8192;
#pragma unroll
        for (int i = 0; i < 4; ++i) {
            int task = t + i * 256;
            int n = task >> 3, s16 = task & 7;
            uint32_t off = (uint32_t)n * 128 + (((uint32_t)s16 * 16) ^ ((uint32_t)(n & 7) << 4));
            cpa16(bb + OFF_BH + off, gh + n * 64 + s16 * 8);
            cpa16(bb + OFF_BL + off, gl + n * 64 + s16 * 8);
        }
    };

    float acc[2][8][4];
#pragma unroll
    for (int i = 0; i < 2; ++i)
#pragma unroll
        for (int j = 0; j < 8; ++j)
#pragma unroll
            for (int q = 0; q < 4; ++q) acc[i][j][q] = 0.f;

    load_a(0);
    issue_b(0, 0);
    asm volatile("cp.async.commit_group;" ::: "memory");
    store_a(0);
    load_a(1);
    issue_b(1, 1);
    asm volatile("cp.async.commit_group;" ::: "memory");
    asm volatile("cp.async.wait_group 1;" ::: "memory");
    __syncthreads();

    for (int c = 0; c < NC; ++c) {
        int stage = c & 1;
        if (c + 1 < NC) store_a(stage ^ 1);
        if (c + 2 < NC) load_a(c + 2);

        uint32_t sb = sbase + stage * STAGE;
#pragma unroll
        for (int ks = 0; ks < 4; ++ks) {
            uint32_t k0b = (uint32_t)ks * 32;
            uint32_t aCol = (k0b + acb) ^ xorv;
            uint32_t bCol = (k0b + bcb) ^ xorv;
            uint32_t ah[2][4], bh[4][4];
            ldsm4(ah[0], sb + OFF_AH + aRowByte0 + aCol);
            ldsm4(ah[1], sb + OFF_AH + aRowByte0 + 16 * 128 + aCol);
#pragma unroll
            for (int p = 0; p < 4; ++p)
                ldsm4(bh[p], sb + OFF_BH + bRowByte0 + p * 16 * 128 + bCol);
#pragma unroll
            for (int mt = 0; mt < 2; ++mt)
#pragma unroll
                for (int nt = 0; nt < 8; ++nt)
                    mma16816(acc[mt][nt], ah[mt],
                             bh[nt >> 1][(nt & 1) * 2], bh[nt >> 1][(nt & 1) * 2 + 1]);

            uint32_t al[2][4];
            ldsm4(al[0], sb + OFF_AL + aRowByte0 + aCol);
            ldsm4(al[1], sb + OFF_AL + aRowByte0 + 16 * 128 + aCol);
#pragma unroll
            for (int mt = 0; mt < 2; ++mt)
#pragma unroll
                for (int nt = 0; nt < 8; ++nt)
                    mma16816(acc[mt][nt], al[mt],
                             bh[nt >> 1][(nt & 1) * 2], bh[nt >> 1][(nt & 1) * 2 + 1]);

            uint32_t bl[4][4];
#pragma unroll
            for (int p = 0; p < 4; ++p)
                ldsm4(bl[p], sb + OFF_BL + bRowByte0 + p * 16 * 128 + bCol);
#pragma unroll
            for (int mt = 0; mt < 2; ++mt)
#pragma unroll
                for (int nt = 0; nt < 8; ++nt)
                    mma16816(acc[mt][nt], ah[mt],
                             bl[nt >> 1][(nt & 1) * 2], bl[nt >> 1][(nt & 1) * 2 + 1]);
        }
        __syncthreads();
        if (c + 2 < NC) {
            issue_b(c + 2, stage);
            asm volatile("cp.async.commit_group;" ::: "memory");
            asm volatile("cp.async.wait_group 1;" ::: "memory");
        } else {
            asm volatile("cp.async.wait_group 0;" ::: "memory");
        }
        __syncthreads();
    }

    int lr = lane >> 2, lc = lane & 3;
#pragma unroll
    for (int mt = 0; mt < 2; ++mt) {
        int r0 = m0 + wm * 32 + mt * 16 + lr;
        int r1 = r0 + 8;
#pragma unroll
        for (int nt = 0; nt < 8; ++nt) {
            int col = wn * 64 + nt * 8 + lc * 2;
            float b0 = bias[col], b1 = bias[col + 1];
            if (r0 < N_NODES) {
                float2 v;
                v.x = fmaxf(acc[mt][nt][0] + b0, 0.f);
                v.y = fmaxf(acc[mt][nt][1] + b1, 0.f);
                *reinterpret_cast<float2*>(out + (size_t)r0 * 128 + col) = v;
            }
            if (r1 < N_NODES) {
                float2 v;
                v.x = fmaxf(acc[mt][nt][2] + b0, 0.f);
                v.y = fmaxf(acc[mt][nt][3] + b1, 0.f);
                *reinterpret_cast<float2*>(out + (size_t)r1 * 128 + col) = v;
            }
        }
    }
}

// ───────────────────────── launch ─────────────────────────
extern "C" void kernel_launch(void* const* d_in, const int* in_sizes, int n_in,
                              void* d_out, int out_size) {
    const float* x          = (const float*)d_in[0];
    const float* edge_attr  = (const float*)d_in[1];
    const float* W_rel      = (const float*)d_in[2];
    const float* We_rel     = (const float*)d_in[3];
    const float* W_self     = (const float*)d_in[4];
    const float* b          = (const float*)d_in[5];
    const int*   edge_index = (const int*)d_in[6];
    float* out = (float*)d_out;

    static bool attr_set = false;
    if (!attr_set) {
        cudaFuncSetAttribute(gemm_mma_kernel,
                             cudaFuncAttributeMaxDynamicSharedMemorySize, SMEM_TOTAL);
        attr_set = true;
    }

    prep_kernel<<<2048, 256>>>(W_rel, We_rel, W_self);

    bucket_kernel<<<(N_REL * N_EDGES + 255) / 256, 256>>>(edge_index);

    escatter_kernel<<<(N_REL * N_EDGES * 4 + 255) / 256, 256>>>(edge_attr, edge_index);

    atile_kernel<<<N_REL * TILES, 256>>>(x);

    overflow_kernel<<<64, 256>>>(x);

    int gblocks = (N_NODES + 127) / 128;  // 782
    gemm_mma_kernel<<<gblocks, 256, SMEM_TOTAL>>>(x, b, out);
}

// round 17
// speedup vs baseline: 1.5073x; 1.5073x over previous
#include <cuda_runtime.h>
#include <cuda_bf16.h>
#include <cstdint>

#define N_NODES 100000
#define N_EDGES 200000
#define D_NODE 128
#define D_EDGE 16
#define N_REL 3

// ───────────────────────── scratch ─────────────────────────
__device__ float g_A[(size_t)N_REL * N_NODES * D_NODE];   // 153.6 MB
__device__ float g_E2[(size_t)N_NODES * 64];              // packed E: [node][r*16..], 25.6 MB
// pre-split weights, 9 chunks × [n=128][k=64] bf16
__device__ __nv_bfloat16 g_Wh[9 * 128 * 64];
__device__ __nv_bfloat16 g_Wl[9 * 128 * 64];

// ─────────────── prep: zero scratch + split weights ───────────────
__global__ void prep_kernel(const float* __restrict__ W_rel,
                            const float* __restrict__ We_rel,
                            const float* __restrict__ W_self) {
    int gtid = blockIdx.x * blockDim.x + threadIdx.x;

    if (gtid < 9 * 128 * 64) {
        int c = gtid / (128 * 64);
        int rem = gtid - c * (128 * 64);
        int n = rem >> 6, j = rem & 63;
        float v = 0.f;
        if (c < 2)       v = W_self[(c * 64 + j) * 128 + n];
        else if (c < 8)  { int r = (c - 2) >> 1, h = (c - 2) & 1;
                           v = W_rel[r * 16384 + (h * 64 + j) * 128 + n]; }
        else             { if (j < 48) v = We_rel[(j >> 4) * 2048 + (j & 15) * 128 + n]; }
        __nv_bfloat16 hb = __float2bfloat16_rn(v);
        g_Wh[gtid] = hb;
        g_Wl[gtid] = __float2bfloat16_rn(v - __bfloat162float(hb));
    }

    const size_t nA = (size_t)N_REL * N_NODES * D_NODE / 4;
    const size_t nE = (size_t)N_NODES * 64 / 4;
    float4 z = make_float4(0.f, 0.f, 0.f, 0.f);
    float4* A4 = reinterpret_cast<float4*>(g_A);
    float4* E4 = reinterpret_cast<float4*>(g_E2);
    size_t stride = (size_t)gridDim.x * blockDim.x;
    for (size_t i = gtid; i < nA; i += stride) A4[i] = z;
    for (size_t i = gtid; i < nE; i += stride) E4[i] = z;
}

// ───────────── scatter (ONE relation per launch → 102 MB L2-resident set) ─────
__global__ void scatter_rel_kernel(const float* __restrict__ x,
                                   const float* __restrict__ edge_attr,
                                   const int*   __restrict__ edge_index,
                                   int r) {
    int w = (blockIdx.x * blockDim.x + threadIdx.x) >> 5;
    int lane = threadIdx.x & 31;
    if (w >= N_EDGES) return;
    int we = r * N_EDGES + w;

    int2 se = reinterpret_cast<const int2*>(edge_index)[we];
    int src = se.x, dst = se.y;

    const float4* xr = reinterpret_cast<const float4*>(x + (size_t)src * D_NODE);
    float4 v = xr[lane];
    float* a = g_A + ((size_t)r * N_NODES + dst) * D_NODE + lane * 4;
    asm volatile("red.global.add.v4.f32 [%0], {%1,%2,%3,%4};"
                 :: "l"(a), "f"(v.x), "f"(v.y), "f"(v.z), "f"(v.w) : "memory");

    if (lane < 4) {
        const float4* er = reinterpret_cast<const float4*>(
            edge_attr + ((size_t)we) * D_EDGE);
        float4 u = er[lane];
        float* ep = g_E2 + (size_t)dst * 64 + r * 16 + lane * 4;
        asm volatile("red.global.add.v4.f32 [%0], {%1,%2,%3,%4};"
                     :: "l"(ep), "f"(u.x), "f"(u.y), "f"(u.z), "f"(u.w) : "memory");
    }
}

// ───────────────── bf16x3 GEMM, full double-buffer + swizzle (R13) ────────────
__device__ __forceinline__ uint32_t smem_u32(const void* p) {
    uint32_t a;
    asm("{ .reg .u64 t; cvta.to.shared.u64 t, %1; cvt.u32.u64 %0, t; }" : "=r"(a) : "l"(p));
    return a;
}
__device__ __forceinline__ void ldsm4(uint32_t* r, uint32_t addr) {
    asm volatile("ldmatrix.sync.aligned.m8n8.x4.shared.b16 {%0,%1,%2,%3}, [%4];"
                 : "=r"(r[0]), "=r"(r[1]), "=r"(r[2]), "=r"(r[3]) : "r"(addr));
}
__device__ __forceinline__ void cpa16(uint32_t s, const void* g) {
    asm volatile("cp.async.ca.shared.global [%0], [%1], 16;" :: "r"(s), "l"(g));
}
__device__ __forceinline__ void mma16816(float* c, const uint32_t* a,
                                         uint32_t b0, uint32_t b1) {
    asm volatile(
        "mma.sync.aligned.m16n8k16.row.col.f32.bf16.bf16.f32 "
        "{%0,%1,%2,%3}, {%4,%5,%6,%7}, {%8,%9}, {%0,%1,%2,%3};"
        : "+f"(c[0]), "+f"(c[1]), "+f"(c[2]), "+f"(c[3])
        : "r"(a[0]), "r"(a[1]), "r"(a[2]), "r"(a[3]), "r"(b0), "r"(b1));
}
__device__ __forceinline__ void split8(const float* f, uint4& hi, uint4& lo) {
    uint32_t h[8], l[8];
#pragma unroll
    for (int j = 0; j < 8; ++j) {
        __nv_bfloat16 hb = __float2bfloat16_rn(f[j]);
        float r = f[j] - __bfloat162float(hb);
        __nv_bfloat16 lb = __float2bfloat16_rn(r);
        h[j] = (uint32_t)__bfloat16_as_ushort(hb);
        l[j] = (uint32_t)__bfloat16_as_ushort(lb);
    }
    hi.x = h[0] | (h[1] << 16); hi.y = h[2] | (h[3] << 16);
    hi.z = h[4] | (h[5] << 16); hi.w = h[6] | (h[7] << 16);
    lo.x = l[0] | (l[1] << 16); lo.y = l[2] | (l[3] << 16);
    lo.z = l[4] | (l[5] << 16); lo.w = l[6] | (l[7] << 16);
}

static constexpr int STAGE    = 65536;
static constexpr int OFF_AH   = 0;
static constexpr int OFF_AL   = 16384;
static constexpr int OFF_BH   = 32768;
static constexpr int OFF_BL   = 49152;
static constexpr int SMEM_TOTAL = 2 * STAGE;   // 131072

static constexpr int NC = 9;

struct Chunk { const float* a; int ld, kb; };

__device__ __forceinline__ Chunk chunk_desc(int c, const float* x) {
    Chunk d;
    if (c < 2)      { d.a = x; d.ld = 128; d.kb = c * 64; }
    else if (c < 8) { int r = (c - 2) >> 1, h = (c - 2) & 1;
                      d.a = g_A + (size_t)r * N_NODES * 128; d.ld = 128; d.kb = h * 64; }
    else            { d.a = g_E2; d.ld = 64; d.kb = 0; }
    return d;
}

__global__ __launch_bounds__(256, 1) void gemm_mma_kernel(
    const float* __restrict__ x,
    const float* __restrict__ bias,
    float* __restrict__ out) {
    extern __shared__ char smem[];
    uint32_t sbase = smem_u32(smem);

    int t = threadIdx.x;
    int wid = t >> 5, lane = t & 31;
    int wm = wid & 3, wn = wid >> 2;
    int m0 = blockIdx.x * 128;

    uint32_t xorv = (uint32_t)(lane & 7) << 4;
    int arow = (lane & 7) + ((lane & 8) ? 8 : 0);
    uint32_t acb = (lane & 16) ? 16 : 0;
    uint32_t aRowByte0 = (uint32_t)(wm * 32 + arow) * 128;
    int brow = (lane & 7) + ((lane & 16) ? 8 : 0);
    uint32_t bcb = (lane & 8) ? 16 : 0;
    uint32_t bRowByte0 = (uint32_t)(wn * 64 + brow) * 128;

    int aRow = t >> 1, aHalf = t & 1;
    uint32_t aStoreRow = (uint32_t)aRow * 128;
    uint32_t aStoreXor = (uint32_t)(aRow & 7) << 4;
    float4 ar[8];

    auto load_a = [&](int c) {
        Chunk d = chunk_desc(c, x);
        int gr = m0 + aRow;
        const float* ap = d.a + (size_t)gr * d.ld + d.kb + aHalf * 32;
        if (gr < N_NODES) {
#pragma unroll
            for (int q = 0; q < 8; ++q)
                ar[q] = *reinterpret_cast<const float4*>(ap + q * 4);
        } else {
#pragma unroll
            for (int q = 0; q < 8; ++q) ar[q] = make_float4(0.f, 0.f, 0.f, 0.f);
        }
    };
    auto store_a = [&](int stage) {
        char* base = smem + stage * STAGE;
#pragma unroll
        for (int g = 0; g < 4; ++g) {
            float f[8];
            f[0]=ar[g*2].x; f[1]=ar[g*2].y; f[2]=ar[g*2].z; f[3]=ar[g*2].w;
            f[4]=ar[g*2+1].x; f[5]=ar[g*2+1].y; f[6]=ar[g*2+1].z; f[7]=ar[g*2+1].w;
            uint4 hi, lo; split8(f, hi, lo);
            uint32_t cbyte = (uint32_t)(64 * aHalf + 16 * g);
            uint32_t off = aStoreRow + (cbyte ^ aStoreXor);
            *reinterpret_cast<uint4*>(base + OFF_AH + off) = hi;
            *reinterpret_cast<uint4*>(base + OFF_AL + off) = lo;
        }
    };
    auto issue_b = [&](int c, int stage) {
        uint32_t bb = sbase + stage * STAGE;
        const __nv_bfloat16* gh = g_Wh + c * 8192;
        const __nv_bfloat16* gl = g_Wl + c * 8192;
#pragma unroll
        for (int i = 0; i < 4; ++i) {
            int task = t + i * 256;
            int n = task >> 3, s16 = task & 7;
            uint32_t off = (uint32_t)n * 128 + (((uint32_t)s16 * 16) ^ ((uint32_t)(n & 7) << 4));
            cpa16(bb + OFF_BH + off, gh + n * 64 + s16 * 8);
            cpa16(bb + OFF_BL + off, gl + n * 64 + s16 * 8);
        }
    };

    float acc[2][8][4];
#pragma unroll
    for (int i = 0; i < 2; ++i)
#pragma unroll
        for (int j = 0; j < 8; ++j)
#pragma unroll
            for (int q = 0; q < 4; ++q) acc[i][j][q] = 0.f;

    load_a(0);
    issue_b(0, 0);
    asm volatile("cp.async.commit_group;" ::: "memory");
    store_a(0);
    load_a(1);
    issue_b(1, 1);
    asm volatile("cp.async.commit_group;" ::: "memory");
    asm volatile("cp.async.wait_group 1;" ::: "memory");
    __syncthreads();

    for (int c = 0; c < NC; ++c) {
        int stage = c & 1;
        if (c + 1 < NC) store_a(stage ^ 1);
        if (c + 2 < NC) load_a(c + 2);

        uint32_t sb = sbase + stage * STAGE;
#pragma unroll
        for (int ks = 0; ks < 4; ++ks) {
            uint32_t k0b = (uint32_t)ks * 32;
            uint32_t aCol = (k0b + acb) ^ xorv;
            uint32_t bCol = (k0b + bcb) ^ xorv;
            uint32_t ah[2][4], bh[4][4];
            ldsm4(ah[0], sb + OFF_AH + aRowByte0 + aCol);
            ldsm4(ah[1], sb + OFF_AH + aRowByte0 + 16 * 128 + aCol);
#pragma unroll
            for (int p = 0; p < 4; ++p)
                ldsm4(bh[p], sb + OFF_BH + bRowByte0 + p * 16 * 128 + bCol);
#pragma unroll
            for (int mt = 0; mt < 2; ++mt)
#pragma unroll
                for (int nt = 0; nt < 8; ++nt)
                    mma16816(acc[mt][nt], ah[mt],
                             bh[nt >> 1][(nt & 1) * 2], bh[nt >> 1][(nt & 1) * 2 + 1]);

            uint32_t al[2][4];
            ldsm4(al[0], sb + OFF_AL + aRowByte0 + aCol);
            ldsm4(al[1], sb + OFF_AL + aRowByte0 + 16 * 128 + aCol);
#pragma unroll
            for (int mt = 0; mt < 2; ++mt)
#pragma unroll
                for (int nt = 0; nt < 8; ++nt)
                    mma16816(acc[mt][nt], al[mt],
                             bh[nt >> 1][(nt & 1) * 2], bh[nt >> 1][(nt & 1) * 2 + 1]);

            uint32_t bl[4][4];
#pragma unroll
            for (int p = 0; p < 4; ++p)
                ldsm4(bl[p], sb + OFF_BL + bRowByte0 + p * 16 * 128 + bCol);
#pragma unroll
            for (int mt = 0; mt < 2; ++mt)
#pragma unroll
                for (int nt = 0; nt < 8; ++nt)
                    mma16816(acc[mt][nt], ah[mt],
                             bl[nt >> 1][(nt & 1) * 2], bl[nt >> 1][(nt & 1) * 2 + 1]);
        }
        __syncthreads();
        if (c + 2 < NC) {
            issue_b(c + 2, stage);
            asm volatile("cp.async.commit_group;" ::: "memory");
            asm volatile("cp.async.wait_group 1;" ::: "memory");
        } else {
            asm volatile("cp.async.wait_group 0;" ::: "memory");
        }
        __syncthreads();
    }

    int lr = lane >> 2, lc = lane & 3;
#pragma unroll
    for (int mt = 0; mt < 2; ++mt) {
        int r0 = m0 + wm * 32 + mt * 16 + lr;
        int r1 = r0 + 8;
#pragma unroll
        for (int nt = 0; nt < 8; ++nt) {
            int col = wn * 64 + nt * 8 + lc * 2;
            float b0 = bias[col], b1 = bias[col + 1];
            if (r0 < N_NODES) {
                float2 v;
                v.x = fmaxf(acc[mt][nt][0] + b0, 0.f);
                v.y = fmaxf(acc[mt][nt][1] + b1, 0.f);
                *reinterpret_cast<float2*>(out + (size_t)r0 * 128 + col) = v;
            }
            if (r1 < N_NODES) {
                float2 v;
                v.x = fmaxf(acc[mt][nt][2] + b0, 0.f);
                v.y = fmaxf(acc[mt][nt][3] + b1, 0.f);
                *reinterpret_cast<float2*>(out + (size_t)r1 * 128 + col) = v;
            }
        }
    }
}

// ───────────────────────── launch ─────────────────────────
extern "C" void kernel_launch(void* const* d_in, const int* in_sizes, int n_in,
                              void* d_out, int out_size) {
    const float* x          = (const float*)d_in[0];
    const float* edge_attr  = (const float*)d_in[1];
    const float* W_rel      = (const float*)d_in[2];
    const float* We_rel     = (const float*)d_in[3];
    const float* W_self     = (const float*)d_in[4];
    const float* b          = (const float*)d_in[5];
    const int*   edge_index = (const int*)d_in[6];
    float* out = (float*)d_out;

    static bool attr_set = false;
    if (!attr_set) {
        cudaFuncSetAttribute(gemm_mma_kernel,
                             cudaFuncAttributeMaxDynamicSharedMemorySize, SMEM_TOTAL);
        attr_set = true;
    }

    prep_kernel<<<2048, 256>>>(W_rel, We_rel, W_self);

    // one relation per launch: per-pass working set = g_A slice (51.2 MB) +
    // x (51.2 MB) ≈ 102 MB < 126 MB L2 → atomic RMW stays in L2
    int blocks = (N_EDGES * 32 + 255) / 256;   // 25000
    scatter_rel_kernel<<<blocks, 256>>>(x, edge_attr, edge_index, 0);
    scatter_rel_kernel<<<blocks, 256>>>(x, edge_attr, edge_index, 1);
    scatter_rel_kernel<<<blocks, 256>>>(x, edge_attr, edge_index, 2);

    int gblocks = (N_NODES + 127) / 128;  // 782
    gemm_mma_kernel<<<gblocks, 256, SMEM_TOTAL>>>(x, b, out);
}